// round 13
// baseline (speedup 1.0000x reference)
#include <cuda_runtime.h>
#include <math.h>

#define Bsz 32
#define Rr  64
#define Ll  4096
#define Hh  768

// Scratch (no device mallocs allowed)
__device__ float g_v[Bsz * Hh];   // v[b,h] = sum_k W[h,k] * ans[b,k]
__device__ float g_t[Bsz * Ll];   // t[b,l] = hidden[b,l,:] . v[b,:]
__device__ float g_sink[4];       // keeps prefetch loads live (never written in practice)

// ---------------------------------------------------------------------------
// Kernel 1: batched GEMV  v[b,h] = W[h,:] . ans[b,:]   (R7 config — proven)
// One warp per h-row, serving 4 batches; W fragment in registers reused
// across batches. block=128, grid=(H/4, B/4)=1536.
// Ends with threadfence + programmatic-launch trigger so the PDL'd k_dot
// can consume g_v as soon as it is globally visible.
// ---------------------------------------------------------------------------
__global__ void k_gemv(const float* __restrict__ W, const float* __restrict__ ans) {
    const int warp = threadIdx.x >> 5;
    const int lane = threadIdx.x & 31;
    const int h    = blockIdx.x * 4 + warp;
    const int b0   = blockIdx.y * 4;

    const float4* wrow = (const float4*)(W + (size_t)h * Hh);
    float4 w[6];
#pragma unroll
    for (int k = 0; k < 6; k++) w[k] = wrow[lane + k * 32];

#pragma unroll
    for (int j = 0; j < 4; j++) {
        const int b = b0 + j;
        const float4* arow = (const float4*)(ans + (size_t)b * Hh);
        float acc = 0.f;
#pragma unroll
        for (int k = 0; k < 6; k++) {
            float4 a4 = arow[lane + k * 32];
            acc += w[k].x * a4.x + w[k].y * a4.y + w[k].z * a4.z + w[k].w * a4.w;
        }
#pragma unroll
        for (int o = 16; o; o >>= 1)
            acc += __shfl_down_sync(0xffffffffu, acc, o);
        if (lane == 0)
            g_v[b * Hh + h] = acc;
    }

    __threadfence();                              // publish g_v
    cudaTriggerProgrammaticLaunchCompletion();    // release PDL successor
}

// ---------------------------------------------------------------------------
// Kernel 2 (PDL secondary): t[b,l] = hidden[b,l,:] . v[b,:]  — 402 MB stream.
// CTAs co-reside with k_gemv: BEFORE the grid-dependency sync each warp
// issues 6 scalar __ldcg sector touches covering its first 2 tokens
// (8192 warps x 6 KB = 48 MB prefetched into L2 *concurrently* with the
// latency-bound k_gemv). After sync: sv from g_v, then the proven stream
// (warp-per-token, 16 tokens/warp, __ldcs).
// ---------------------------------------------------------------------------
__global__ void __launch_bounds__(256, 8)
k_dot(const float* __restrict__ hidden) {
    __shared__ float4 sv[Hh / 4];
    const int b    = blockIdx.y;
    const int warp = threadIdx.x >> 5;
    const int lane = threadIdx.x & 31;
    const int l0   = blockIdx.x * 128 + warp * 16;   // this warp's 16 tokens

    // ---- Prefetch own first 2 tokens (independent of g_v) -----------------
    float p0 = 0.f, p1 = 0.f;
    {
        const float* row0 = hidden + ((size_t)b * Ll + l0) * Hh;
#pragma unroll
        for (int r = 0; r < 3; r++) {
            p0 += __ldcg(row0 + (r * 32 + lane) * 8);            // token l0
            p1 += __ldcg(row0 + Hh + (r * 32 + lane) * 8);       // token l0+1
        }
    }

    // ---- Wait for k_gemv's g_v (PDL; falls back to full-completion wait) --
    cudaGridDependencySynchronize();
    __threadfence();

    for (int i = threadIdx.x; i < Hh / 4; i += 256)
        sv[i] = ((const float4*)(g_v + b * Hh))[i];
    __syncthreads();

    const float4* base = (const float4*)(hidden + ((size_t)b * Ll + l0) * Hh) + lane;

    for (int i = 0; i < 16; i++) {
        float acc = 0.f;
#pragma unroll
        for (int k = 0; k < 6; k++) {
            float4 x  = __ldcs(base + (size_t)i * (Hh / 4) + k * 32);
            float4 vv = sv[lane + k * 32];
            acc += x.x * vv.x + x.y * vv.y + x.z * vv.z + x.w * vv.w;
        }
#pragma unroll
        for (int o = 16; o; o >>= 1)
            acc += __shfl_down_sync(0xffffffffu, acc, o);
        if (lane == 0)
            g_t[b * Ll + l0 + i] = acc;
    }

    // Keep prefetch loads live (data-dependent, never true).
    if (p0 + p1 == 123456789.0f)
        g_sink[0] = p0;

    __threadfence();                              // publish g_t
    cudaTriggerProgrammaticLaunchCompletion();    // release k_score
}

// ---------------------------------------------------------------------------
// Kernel 3 (PDL secondary): span-mean over t, mask, bias, softmax per b row.
// One block per b; 8 warps, warp per span; t is L2-hot.
// NOTE: rubric_mask is bool -> harness promotes to int32.
// ---------------------------------------------------------------------------
__global__ void k_score(const int* __restrict__ span,
                        const int* __restrict__ mask,
                        const float* __restrict__ bias,
                        float* __restrict__ out) {
    cudaGridDependencySynchronize();
    __threadfence();

    __shared__ float sc[Rr];
    const int b    = blockIdx.x;
    const int warp = threadIdx.x >> 5;
    const int lane = threadIdx.x & 31;

    for (int r = warp; r < Rr; r += 8) {
        float score;
        if (mask[b * Rr + r] == 0) {
            score = -INFINITY;
        } else {
            const int s = span[(b * Rr + r) * 2 + 0];
            const int e = span[(b * Rr + r) * 2 + 1];
            const float* t = g_t + b * Ll;
            float acc = 0.f;
            for (int idx = s + lane; idx < e; idx += 32)
                acc += t[idx];
#pragma unroll
            for (int o = 16; o; o >>= 1)
                acc += __shfl_down_sync(0xffffffffu, acc, o);
            int len = e - s; if (len < 1) len = 1;
            score = acc / (float)len + bias[0];
        }
        if (lane == 0) sc[r] = score;
    }
    __syncthreads();

    if (threadIdx.x < 32) {
        const int tid = threadIdx.x;
        float a0 = sc[tid], a1 = sc[tid + 32];
        float m = fmaxf(a0, a1);
#pragma unroll
        for (int o = 16; o; o >>= 1)
            m = fmaxf(m, __shfl_xor_sync(0xffffffffu, m, o));
        float e0 = expf(a0 - m);
        float e1 = expf(a1 - m);
        float ssum = e0 + e1;
#pragma unroll
        for (int o = 16; o; o >>= 1)
            ssum += __shfl_xor_sync(0xffffffffu, ssum, o);
        out[b * Rr + tid]      = e0 / ssum;
        out[b * Rr + tid + 32] = e1 / ssum;
    }
}

// ---------------------------------------------------------------------------
extern "C" void kernel_launch(void* const* d_in, const int* in_sizes, int n_in,
                              void* d_out, int out_size) {
    const float* ans    = (const float*)d_in[0];   // (32, 768) f32
    const float* hidden = (const float*)d_in[1];   // (32, 4096, 768) f32
    const int*   span   = (const int*)d_in[2];     // (32, 64, 2) i32
    const int*   mask   = (const int*)d_in[3];     // (32, 64) bool -> i32
    const float* W      = (const float*)d_in[4];   // (1, 768, 768) f32
    const float* bias   = (const float*)d_in[5];   // (1,) f32
    float*       out    = (float*)d_out;           // (32, 64) f32

    k_gemv <<< dim3(Hh / 4, Bsz / 4), 128 >>> (W, ans);

    cudaLaunchAttribute at[1];
    at[0].id = cudaLaunchAttributeProgrammaticStreamSerialization;
    at[0].val.programmaticStreamSerializationAllowed = 1;

    {   // k_dot as PDL secondary of k_gemv
        cudaLaunchConfig_t cfg = {};
        cfg.gridDim  = dim3(Ll / 128, Bsz);
        cfg.blockDim = dim3(256);
        cfg.stream   = 0;
        cfg.attrs    = at;
        cfg.numAttrs = 1;
        cudaLaunchKernelEx(&cfg, k_dot, hidden);
    }
    {   // k_score as PDL secondary of k_dot
        cudaLaunchConfig_t cfg = {};
        cfg.gridDim  = dim3(Bsz);
        cfg.blockDim = dim3(256);
        cfg.stream   = 0;
        cfg.attrs    = at;
        cfg.numAttrs = 1;
        cudaLaunchKernelEx(&cfg, k_score, span, mask, bias, out);
    }
}